// round 10
// baseline (speedup 1.0000x reference)
#include <cuda_runtime.h>
#include <cuda_bf16.h>
#include <cstdint>

// BahdanauAttention with size-1 attention axis:
//   softmax over length-1 axis == 1.0 -> attention_weights = ones(B,1,1)
//   context = features (bit-exact copy). Score GEMMs are dead code.
// Pure HBM streaming copy: 128 MiB read + 128 MiB write + 64 KiB fill.
//
// This round: 256-bit global accesses (ld/st.global.v8.f32, sm_100+ only,
// PTX-only — ptxas never auto-emits v8). Halves LSU transactions per byte.
// Everything else is the converged config: 2048x256, front-batched loads.

static constexpr int Bsz = 16384;
static constexpr int Dsz = 2048;
static constexpr int CTX_V8 = (Bsz * Dsz) / 8;   // 4,194,304 float8 (2^22)
static constexpr int AW_V8  = Bsz / 8;           // 2,048 float8

static constexpr int THREADS = 256;
static constexpr int BLOCKS  = 2048;
static constexpr int NTHREADS = THREADS * BLOCKS;        // 524,288 = 2^19
static constexpr int V8_PER_THREAD = CTX_V8 / NTHREADS;  // 8, exact

struct __align__(32) f8 { float v[8]; };

__device__ __forceinline__ f8 ldg_v8(const float* p) {
    f8 r;
    asm volatile("ld.global.v8.f32 {%0,%1,%2,%3,%4,%5,%6,%7}, [%8];"
        : "=f"(r.v[0]), "=f"(r.v[1]), "=f"(r.v[2]), "=f"(r.v[3]),
          "=f"(r.v[4]), "=f"(r.v[5]), "=f"(r.v[6]), "=f"(r.v[7])
        : "l"(p));
    return r;
}

__device__ __forceinline__ void stg_v8(float* p, const f8& r) {
    asm volatile("st.global.v8.f32 [%0], {%1,%2,%3,%4,%5,%6,%7,%8};"
        :: "l"(p),
           "f"(r.v[0]), "f"(r.v[1]), "f"(r.v[2]), "f"(r.v[3]),
           "f"(r.v[4]), "f"(r.v[5]), "f"(r.v[6]), "f"(r.v[7])
        : "memory");
}

__global__ void __launch_bounds__(THREADS, 2)
bahdanau_copy_kernel(const float* __restrict__ features, float* __restrict__ out) {
    int tid = blockIdx.x * THREADS + threadIdx.x;

    // 8 x 256-bit loads front-batched (64 floats in flight), then 8 stores.
    f8 a[V8_PER_THREAD];
    #pragma unroll
    for (int j = 0; j < V8_PER_THREAD; j++)
        a[j] = ldg_v8(features + (size_t)(tid + j * NTHREADS) * 8);
    #pragma unroll
    for (int j = 0; j < V8_PER_THREAD; j++)
        stg_v8(out + (size_t)(tid + j * NTHREADS) * 8, a[j]);

    // Trailing ones for attention_weights: one 256-bit store per thread
    // for the first 2048 threads.
    if (tid < AW_V8) {
        f8 ones;
        #pragma unroll
        for (int j = 0; j < 8; j++) ones.v[j] = 1.f;
        stg_v8(out + (size_t)CTX_V8 * 8 + (size_t)tid * 8, ones);
    }
}

extern "C" void kernel_launch(void* const* d_in, const int* in_sizes, int n_in,
                              void* d_out, int out_size) {
    const float* features = (const float*)d_in[0];
    float* out = (float*)d_out;
    bahdanau_copy_kernel<<<BLOCKS, THREADS>>>(features, out);
}